// round 1
// baseline (speedup 1.0000x reference)
#include <cuda_runtime.h>

// Problem constants (fixed by the dataset)
#define D   64
#define P   3
#define H   128
#define O   128
#define NMAX   100000
#define NCMAX  50000
#define EMAX   1600000

// ---------------- scratch (device globals; no allocation allowed) ----------
__device__ float g_A[NMAX * H];        // per-source-node layer-1 partial (+b1)
__device__ float g_B[NCMAX * H];       // per-center layer-1 partial
__device__ int   g_rowptr[NCMAX + 1];  // CSR row pointers (by dst)
__device__ int   g_cursor[NCMAX];      // counts -> scatter cursors
__device__ int   g_esrc[EMAX];         // src id per CSR-sorted edge

// ---------------------------------------------------------------------------
// A[n][h] = sum_d x[n][d]*W1[d][h] + sum_p pos[n][p]*W1[64+p][h] + b1[h]
// One block = 8 rows, 128 threads (one output column each), W1 in smem.
// ---------------------------------------------------------------------------
__global__ void k_precompute_A(const float* __restrict__ x,
                               const float* __restrict__ pos,
                               const float* __restrict__ W1,
                               const float* __restrict__ b1, int N)
{
    __shared__ float W1s[(D + P) * H];
    __shared__ float xs[D + P];
    const int tid = threadIdx.x;  // 0..127
    for (int i = tid; i < (D + P) * H; i += 128) W1s[i] = W1[i];
    const float bias = b1[tid];
    __syncthreads();

    const int base = blockIdx.x * 8;
    for (int r = 0; r < 8; r++) {
        const int n = base + r;
        if (n >= N) break;
        if (tid < D) xs[tid] = x[n * D + tid];
        if (tid < P) xs[D + tid] = pos[n * P + tid];
        __syncthreads();
        float s = bias;
#pragma unroll
        for (int d = 0; d < D + P; d++) s += xs[d] * W1s[d * H + tid];
        g_A[n * H + tid] = s;
        __syncthreads();
    }
}

// B[c][h] = sum_p pos_c[c][p] * W1[64+p][h]
__global__ void k_precompute_B(const float* __restrict__ pos_c,
                               const float* __restrict__ W1, int NC)
{
    const int idx = blockIdx.x * blockDim.x + threadIdx.x;
    if (idx >= NC * H) return;
    const int c = idx >> 7;
    const int h = idx & 127;
    const float p0 = pos_c[c * 3 + 0];
    const float p1 = pos_c[c * 3 + 1];
    const float p2 = pos_c[c * 3 + 2];
    g_B[idx] = p0 * W1[(D + 0) * H + h]
             + p1 * W1[(D + 1) * H + h]
             + p2 * W1[(D + 2) * H + h];
}

// ------------------------- CSR build ---------------------------------------
__global__ void k_zero_counts(int NC)
{
    const int i = blockIdx.x * blockDim.x + threadIdx.x;
    if (i < NC) g_cursor[i] = 0;
}

__global__ void k_histogram(const int* __restrict__ dst, int E)
{
    const int i = blockIdx.x * blockDim.x + threadIdx.x;
    if (i < E) atomicAdd(&g_cursor[dst[i]], 1);
}

// Single-block exclusive scan over NC counts (tiles of 1024, Kogge-Stone).
// Writes rowptr[0..NC] and resets cursor[i] = rowptr[i] for the scatter pass.
__global__ void k_scan(int NC)
{
    __shared__ int s[1024];
    __shared__ int carry;
    const int tid = threadIdx.x;
    if (tid == 0) carry = 0;
    __syncthreads();

    const int ntiles = (NC + 1023) >> 10;
    for (int tile = 0; tile < ntiles; tile++) {
        const int i = (tile << 10) + tid;
        const int v = (i < NC) ? g_cursor[i] : 0;
        s[tid] = v;
        __syncthreads();
#pragma unroll
        for (int off = 1; off < 1024; off <<= 1) {
            const int add = (tid >= off) ? s[tid - off] : 0;
            __syncthreads();
            s[tid] += add;
            __syncthreads();
        }
        const int excl = s[tid] - v + carry;   // carry stable here
        if (i < NC) {
            g_rowptr[i] = excl;
            g_cursor[i] = excl;
        }
        __syncthreads();
        if (tid == 0) carry += s[1023];
        __syncthreads();
    }
    if (tid == 0) g_rowptr[NC] = carry;
}

__global__ void k_scatter(const int* __restrict__ src,
                          const int* __restrict__ dst, int E)
{
    const int i = blockIdx.x * blockDim.x + threadIdx.x;
    if (i < E) {
        const int p = atomicAdd(&g_cursor[dst[i]], 1);
        g_esrc[p] = src[i];
    }
}

// ---------------------------------------------------------------------------
// Aggregate: persistent blocks, one center at a time.
//   thread t: j = t&127 (output column), half = t>>7 (k in [0,64) or [64,128))
//   W2 half-column held in registers as 32 packed f32x2 values.
//   per edge: h1 = relu(A[src]-B[c]) into smem, then packed-FMA dot,
//   halves combined via smem, running max in registers, single store.
// ---------------------------------------------------------------------------
__device__ __forceinline__ void ffma2(unsigned long long& acc,
                                      unsigned long long a,
                                      unsigned long long b)
{
    asm("fma.rn.f32x2 %0, %1, %2, %0;" : "+l"(acc) : "l"(a), "l"(b));
}

#define EB 8   // edges per batch

__global__ void __launch_bounds__(256, 2)
k_aggregate(const float* __restrict__ W2, const float* __restrict__ b2,
            float* __restrict__ out, int NC)
{
    __shared__ float bsh[H];
    __shared__ __align__(16) float h1s[EB][H];
    __shared__ float psum[EB][H];

    const int t = threadIdx.x;
    const int j = t & 127;
    const int half = t >> 7;

    // W2[:,j] half-column, packed pairs (lo=even k, hi=odd k)
    unsigned long long wreg[32];
#pragma unroll
    for (int m = 0; m < 32; m++) {
        const int k = half * 64 + 2 * m;
        const float lo = W2[k * O + j];
        const float hi = W2[(k + 1) * O + j];
        asm("mov.b64 %0, {%1, %2};" : "=l"(wreg[m]) : "f"(lo), "f"(hi));
    }
    const float b2j = b2[j];

    for (int c = blockIdx.x; c < NC; c += gridDim.x) {
        const int beg = g_rowptr[c];
        const int end = g_rowptr[c + 1];
        if (t < H) bsh[t] = g_B[c * H + t];
        __syncthreads();

        float accj = -__int_as_float(0x7f800000);  // -inf
        float dloc[EB];

        for (int e0 = beg; e0 < end; e0 += EB) {
            const int ne = min(EB, end - e0);

            // phase 1: h1 rows for up to EB edges (2 edges per pass)
#pragma unroll
            for (int i = 0; i < EB; i += 2) {
                const int e = i + half;
                if (e < ne) {
                    const int s = g_esrc[e0 + e];
                    h1s[e][j] = fmaxf(g_A[s * H + j] - bsh[j], 0.0f);
                }
            }
            __syncthreads();

            // phase 2: packed-FMA half-dots
#pragma unroll
            for (int e = 0; e < EB; e++) {
                if (e < ne) {
                    unsigned long long a0 = 0ull, a1 = 0ull;
                    const ulonglong2* hp =
                        reinterpret_cast<const ulonglong2*>(&h1s[e][half * 64]);
#pragma unroll
                    for (int m = 0; m < 16; m++) {
                        const ulonglong2 hh = hp[m];
                        ffma2(a0, wreg[2 * m + 0], hh.x);
                        ffma2(a1, wreg[2 * m + 1], hh.y);
                    }
                    const float d =
                        __uint_as_float((unsigned)a0) +
                        __uint_as_float((unsigned)(a0 >> 32)) +
                        __uint_as_float((unsigned)a1) +
                        __uint_as_float((unsigned)(a1 >> 32));
                    if (half) psum[e][j] = d;
                    else      dloc[e] = d;
                }
            }
            __syncthreads();

            // phase 3: combine halves, running max (half 0 only)
            if (!half) {
#pragma unroll
                for (int e = 0; e < EB; e++) {
                    if (e < ne) accj = fmaxf(accj, dloc[e] + psum[e][j]);
                }
            }
        }

        if (!half) out[c * O + j] = (end > beg) ? (accj + b2j) : 0.0f;
        __syncthreads();
    }
}

// ---------------------------------------------------------------------------
extern "C" void kernel_launch(void* const* d_in, const int* in_sizes, int n_in,
                              void* d_out, int out_size)
{
    const float* x     = (const float*)d_in[0];
    // d_in[1] = x_c : only its shape matters (defines NC)
    const float* pos   = (const float*)d_in[2];
    const float* pos_c = (const float*)d_in[3];
    const int*   src   = (const int*)d_in[4];
    const int*   dst   = (const int*)d_in[5];
    const float* W1    = (const float*)d_in[6];
    const float* b1    = (const float*)d_in[7];
    const float* W2    = (const float*)d_in[8];
    const float* b2    = (const float*)d_in[9];
    float* out = (float*)d_out;

    const int N  = in_sizes[0] / D;
    const int NC = in_sizes[1] / O;
    const int E  = in_sizes[4];

    k_precompute_A<<<(N + 7) / 8, 128>>>(x, pos, W1, b1, N);
    k_precompute_B<<<(NC * H + 255) / 256, 256>>>(pos_c, W1, NC);
    k_zero_counts<<<(NC + 255) / 256, 256>>>(NC);
    k_histogram<<<(E + 255) / 256, 256>>>(dst, E);
    k_scan<<<1, 1024>>>(NC);
    k_scatter<<<(E + 255) / 256, 256>>>(src, dst, E);
    k_aggregate<<<592, 256>>>(W2, b2, out, NC);
}

// round 2
// speedup vs baseline: 1.0006x; 1.0006x over previous
#include <cuda_runtime.h>

// Problem constants (fixed by the dataset)
#define D   64
#define P   3
#define H   128
#define O   128
#define NMAX   100000
#define NCMAX  50000
#define EMAX   1600000

// ---------------- scratch (device globals; no allocation allowed) ----------
__device__ float g_A[NMAX * H];        // per-source-node layer-1 partial (+b1)
__device__ float g_B[NCMAX * H];       // per-center layer-1 partial
__device__ int   g_rowptr[NCMAX + 1];  // CSR row pointers (by dst)
__device__ int   g_cursor[NCMAX];      // counts -> scatter cursors
__device__ int   g_esrc[EMAX];         // src id per CSR-sorted edge

// ---------------------------------------------------------------------------
// A[n][h] = sum_d x[n][d]*W1[d][h] + sum_p pos[n][p]*W1[64+p][h] + b1[h]
// One block = 8 rows, 128 threads (one output column each), W1 in smem.
// ---------------------------------------------------------------------------
__global__ void k_precompute_A(const float* __restrict__ x,
                               const float* __restrict__ pos,
                               const float* __restrict__ W1,
                               const float* __restrict__ b1, int N)
{
    __shared__ float W1s[(D + P) * H];
    __shared__ float xs[D + P];
    const int tid = threadIdx.x;  // 0..127
    for (int i = tid; i < (D + P) * H; i += 128) W1s[i] = W1[i];
    const float bias = b1[tid];
    __syncthreads();

    const int base = blockIdx.x * 8;
    for (int r = 0; r < 8; r++) {
        const int n = base + r;
        if (n >= N) break;
        if (tid < D) xs[tid] = x[n * D + tid];
        if (tid < P) xs[D + tid] = pos[n * P + tid];
        __syncthreads();
        float s = bias;
#pragma unroll
        for (int d = 0; d < D + P; d++) s += xs[d] * W1s[d * H + tid];
        g_A[n * H + tid] = s;
        __syncthreads();
    }
}

// B[c][h] = sum_p pos_c[c][p] * W1[64+p][h]
__global__ void k_precompute_B(const float* __restrict__ pos_c,
                               const float* __restrict__ W1, int NC)
{
    const int idx = blockIdx.x * blockDim.x + threadIdx.x;
    if (idx >= NC * H) return;
    const int c = idx >> 7;
    const int h = idx & 127;
    const float p0 = pos_c[c * 3 + 0];
    const float p1 = pos_c[c * 3 + 1];
    const float p2 = pos_c[c * 3 + 2];
    g_B[idx] = p0 * W1[(D + 0) * H + h]
             + p1 * W1[(D + 1) * H + h]
             + p2 * W1[(D + 2) * H + h];
}

// ------------------------- CSR build ---------------------------------------
__global__ void k_zero_counts(int NC)
{
    const int i = blockIdx.x * blockDim.x + threadIdx.x;
    if (i < NC) g_cursor[i] = 0;
}

__global__ void k_histogram(const int* __restrict__ dst, int E)
{
    const int i = blockIdx.x * blockDim.x + threadIdx.x;
    if (i < E) atomicAdd(&g_cursor[dst[i]], 1);
}

// Single-block exclusive scan over NC counts (tiles of 1024, Kogge-Stone).
// Writes rowptr[0..NC] and resets cursor[i] = rowptr[i] for the scatter pass.
__global__ void k_scan(int NC)
{
    __shared__ int s[1024];
    __shared__ int carry;
    const int tid = threadIdx.x;
    if (tid == 0) carry = 0;
    __syncthreads();

    const int ntiles = (NC + 1023) >> 10;
    for (int tile = 0; tile < ntiles; tile++) {
        const int i = (tile << 10) + tid;
        const int v = (i < NC) ? g_cursor[i] : 0;
        s[tid] = v;
        __syncthreads();
#pragma unroll
        for (int off = 1; off < 1024; off <<= 1) {
            const int add = (tid >= off) ? s[tid - off] : 0;
            __syncthreads();
            s[tid] += add;
            __syncthreads();
        }
        const int excl = s[tid] - v + carry;   // carry stable here
        if (i < NC) {
            g_rowptr[i] = excl;
            g_cursor[i] = excl;
        }
        __syncthreads();
        if (tid == 0) carry += s[1023];
        __syncthreads();
    }
    if (tid == 0) g_rowptr[NC] = carry;
}

__global__ void k_scatter(const int* __restrict__ src,
                          const int* __restrict__ dst, int E)
{
    const int i = blockIdx.x * blockDim.x + threadIdx.x;
    if (i < E) {
        const int p = atomicAdd(&g_cursor[dst[i]], 1);
        g_esrc[p] = src[i];
    }
}

// ---------------------------------------------------------------------------
// Aggregate: persistent blocks, one center at a time.
//   thread t: j = t&127 (output column), half = t>>7 (k in [0,64) or [64,128))
//   W2 half-column held in registers as 32 packed f32x2 values.
//   per edge: h1 = relu(A[src]-B[c]) into smem, then packed-FMA dot,
//   halves combined via smem, running max in registers, single store.
// ---------------------------------------------------------------------------
__device__ __forceinline__ void ffma2(unsigned long long& acc,
                                      unsigned long long a,
                                      unsigned long long b)
{
    asm("fma.rn.f32x2 %0, %1, %2, %0;" : "+l"(acc) : "l"(a), "l"(b));
}

#define EB 8   // edges per batch

__global__ void __launch_bounds__(256, 2)
k_aggregate(const float* __restrict__ W2, const float* __restrict__ b2,
            float* __restrict__ out, int NC)
{
    __shared__ float bsh[H];
    __shared__ __align__(16) float h1s[EB][H];
    __shared__ float psum[EB][H];

    const int t = threadIdx.x;
    const int j = t & 127;
    const int half = t >> 7;

    // W2[:,j] half-column, packed pairs (lo=even k, hi=odd k)
    unsigned long long wreg[32];
#pragma unroll
    for (int m = 0; m < 32; m++) {
        const int k = half * 64 + 2 * m;
        const float lo = W2[k * O + j];
        const float hi = W2[(k + 1) * O + j];
        asm("mov.b64 %0, {%1, %2};" : "=l"(wreg[m]) : "f"(lo), "f"(hi));
    }
    const float b2j = b2[j];

    for (int c = blockIdx.x; c < NC; c += gridDim.x) {
        const int beg = g_rowptr[c];
        const int end = g_rowptr[c + 1];
        if (t < H) bsh[t] = g_B[c * H + t];
        __syncthreads();

        float accj = -__int_as_float(0x7f800000);  // -inf
        float dloc[EB];

        for (int e0 = beg; e0 < end; e0 += EB) {
            const int ne = min(EB, end - e0);

            // phase 1: h1 rows for up to EB edges (2 edges per pass)
#pragma unroll
            for (int i = 0; i < EB; i += 2) {
                const int e = i + half;
                if (e < ne) {
                    const int s = g_esrc[e0 + e];
                    h1s[e][j] = fmaxf(g_A[s * H + j] - bsh[j], 0.0f);
                }
            }
            __syncthreads();

            // phase 2: packed-FMA half-dots
#pragma unroll
            for (int e = 0; e < EB; e++) {
                if (e < ne) {
                    unsigned long long a0 = 0ull, a1 = 0ull;
                    const ulonglong2* hp =
                        reinterpret_cast<const ulonglong2*>(&h1s[e][half * 64]);
#pragma unroll
                    for (int m = 0; m < 16; m++) {
                        const ulonglong2 hh = hp[m];
                        ffma2(a0, wreg[2 * m + 0], hh.x);
                        ffma2(a1, wreg[2 * m + 1], hh.y);
                    }
                    const float d =
                        __uint_as_float((unsigned)a0) +
                        __uint_as_float((unsigned)(a0 >> 32)) +
                        __uint_as_float((unsigned)a1) +
                        __uint_as_float((unsigned)(a1 >> 32));
                    if (half) psum[e][j] = d;
                    else      dloc[e] = d;
                }
            }
            __syncthreads();

            // phase 3: combine halves, running max (half 0 only)
            if (!half) {
#pragma unroll
                for (int e = 0; e < EB; e++) {
                    if (e < ne) accj = fmaxf(accj, dloc[e] + psum[e][j]);
                }
            }
        }

        if (!half) out[c * O + j] = (end > beg) ? (accj + b2j) : 0.0f;
        __syncthreads();
    }
}

// ---------------------------------------------------------------------------
extern "C" void kernel_launch(void* const* d_in, const int* in_sizes, int n_in,
                              void* d_out, int out_size)
{
    const float* x     = (const float*)d_in[0];
    // d_in[1] = x_c : only its shape matters (defines NC)
    const float* pos   = (const float*)d_in[2];
    const float* pos_c = (const float*)d_in[3];
    const int*   src   = (const int*)d_in[4];
    const int*   dst   = (const int*)d_in[5];
    const float* W1    = (const float*)d_in[6];
    const float* b1    = (const float*)d_in[7];
    const float* W2    = (const float*)d_in[8];
    const float* b2    = (const float*)d_in[9];
    float* out = (float*)d_out;

    const int N  = in_sizes[0] / D;
    const int NC = in_sizes[1] / O;
    const int E  = in_sizes[4];

    k_precompute_A<<<(N + 7) / 8, 128>>>(x, pos, W1, b1, N);
    k_precompute_B<<<(NC * H + 255) / 256, 256>>>(pos_c, W1, NC);
    k_zero_counts<<<(NC + 255) / 256, 256>>>(NC);
    k_histogram<<<(E + 255) / 256, 256>>>(dst, E);
    k_scan<<<1, 1024>>>(NC);
    k_scatter<<<(E + 255) / 256, 256>>>(src, dst, E);
    k_aggregate<<<592, 256>>>(W2, b2, out, NC);
}

// round 5
// speedup vs baseline: 1.7851x; 1.7840x over previous
#include <cuda_runtime.h>

// Problem constants (fixed by the dataset)
#define D   64
#define P   3
#define H   128
#define O   128
#define NMAX   100000
#define NCMAX  50000
#define EMAX   1600000
#define TILE   128

// ---------------- scratch (device globals; no allocation allowed) ----------
__device__ float        g_A[NMAX * H];       // per-source layer-1 partial (+b1)
__device__ float        g_B[NCMAX * H];      // per-center layer-1 partial
__device__ int          g_rowptr[NCMAX + 1];
__device__ int          g_cursor[NCMAX];
__device__ int          g_esrc[EMAX];        // CSR-sorted src
__device__ int          g_edst[EMAX];        // CSR-sorted dst (non-decreasing)
__device__ unsigned int g_enc[NCMAX * O];    // encoded-uint running max
__device__ int          g_tilectr;           // work-stealing counter

// ======================= helpers ===========================================
__device__ __forceinline__ unsigned smem_u32(const void* p) {
    unsigned a;
    asm("{ .reg .u64 t; cvta.to.shared.u64 t, %1; cvt.u32.u64 %0, t; }"
        : "=r"(a) : "l"(p));
    return a;
}

// order-preserving float<->uint encode for atomicMax
__device__ __forceinline__ unsigned fenc(float f) {
    unsigned u = __float_as_uint(f);
    return (u & 0x80000000u) ? ~u : (u | 0x80000000u);
}
__device__ __forceinline__ float fdec(unsigned u) {
    return __uint_as_float((u & 0x80000000u) ? (u & 0x7fffffffu) : ~u);
}
#define ENC_NEG_INF 0x007FFFFFu

// baseline-PTX tensor ops (valid on sm_80+, hence plain sm_103)
__device__ __forceinline__ void ldsm4(unsigned& r0, unsigned& r1,
                                      unsigned& r2, unsigned& r3, unsigned addr)
{
    asm volatile("ldmatrix.sync.aligned.m8n8.x4.shared.b16 {%0,%1,%2,%3}, [%4];"
                 : "=r"(r0), "=r"(r1), "=r"(r2), "=r"(r3) : "r"(addr));
}
__device__ __forceinline__ void mma16816(float* d, const unsigned* a,
                                         unsigned b0, unsigned b1)
{
    asm volatile("mma.sync.aligned.m16n8k16.row.col.f32.bf16.bf16.f32 "
                 "{%0,%1,%2,%3}, {%4,%5,%6,%7}, {%8,%9}, {%0,%1,%2,%3};"
                 : "+f"(d[0]), "+f"(d[1]), "+f"(d[2]), "+f"(d[3])
                 : "r"(a[0]), "r"(a[1]), "r"(a[2]), "r"(a[3]),
                   "r"(b0), "r"(b1));
}

// ---------------------------------------------------------------------------
// A[n][h] = x[n] @ W1[:64] + pos[n] @ W1[64:67] + b1
// ---------------------------------------------------------------------------
__global__ void k_precompute_A(const float* __restrict__ x,
                               const float* __restrict__ pos,
                               const float* __restrict__ W1,
                               const float* __restrict__ b1, int N)
{
    __shared__ float W1s[(D + P) * H];
    __shared__ float xs[D + P];
    const int tid = threadIdx.x;
    for (int i = tid; i < (D + P) * H; i += 128) W1s[i] = W1[i];
    const float bias = b1[tid];
    __syncthreads();

    const int base = blockIdx.x * 8;
    for (int r = 0; r < 8; r++) {
        const int n = base + r;
        if (n >= N) break;
        if (tid < D) xs[tid] = x[n * D + tid];
        if (tid < P) xs[D + tid] = pos[n * P + tid];
        __syncthreads();
        float s = bias;
#pragma unroll
        for (int d = 0; d < D + P; d++) s += xs[d] * W1s[d * H + tid];
        g_A[n * H + tid] = s;
        __syncthreads();
    }
}

__global__ void k_precompute_B(const float* __restrict__ pos_c,
                               const float* __restrict__ W1, int NC)
{
    const int idx = blockIdx.x * blockDim.x + threadIdx.x;
    if (idx >= NC * H) return;
    const int c = idx >> 7;
    const int h = idx & 127;
    g_B[idx] = pos_c[c * 3 + 0] * W1[(D + 0) * H + h]
             + pos_c[c * 3 + 1] * W1[(D + 1) * H + h]
             + pos_c[c * 3 + 2] * W1[(D + 2) * H + h];
}

// ------------------------- CSR + output init -------------------------------
__global__ void k_init(int NC)
{
    const int i = blockIdx.x * blockDim.x + threadIdx.x;
    if (i == 0) g_tilectr = 0;
    if (i < NC) g_cursor[i] = 0;
    if (i < NC * O) g_enc[i] = ENC_NEG_INF;
}

__global__ void k_histogram(const int* __restrict__ dst, int E)
{
    const int i = blockIdx.x * blockDim.x + threadIdx.x;
    if (i < E) atomicAdd(&g_cursor[dst[i]], 1);
}

__global__ void k_scan(int NC)
{
    __shared__ int s[1024];
    __shared__ int carry;
    const int tid = threadIdx.x;
    if (tid == 0) carry = 0;
    __syncthreads();

    const int ntiles = (NC + 1023) >> 10;
    for (int tile = 0; tile < ntiles; tile++) {
        const int i = (tile << 10) + tid;
        const int v = (i < NC) ? g_cursor[i] : 0;
        s[tid] = v;
        __syncthreads();
#pragma unroll
        for (int off = 1; off < 1024; off <<= 1) {
            const int add = (tid >= off) ? s[tid - off] : 0;
            __syncthreads();
            s[tid] += add;
            __syncthreads();
        }
        const int excl = s[tid] - v + carry;
        if (i < NC) {
            g_rowptr[i] = excl;
            g_cursor[i] = excl;
        }
        __syncthreads();
        if (tid == 0) carry += s[1023];
        __syncthreads();
    }
    if (tid == 0) g_rowptr[NC] = carry;
}

__global__ void k_scatter(const int* __restrict__ src,
                          const int* __restrict__ dst, int E)
{
    const int i = blockIdx.x * blockDim.x + threadIdx.x;
    if (i < E) {
        const int p = atomicAdd(&g_cursor[dst[i]], 1);
        g_esrc[p] = src[i];
        g_edst[p] = dst[i];
    }
}

// ---------------------------------------------------------------------------
// Aggregate via mma.sync (baseline HMMA path; tcgen05 unavailable on sm_103):
//  tiles of 128 CSR-sorted edges. h1 = relu(A[src]-B[dst]) split to bf16
//  hi/lo in smem; D = h_hi@Whi + h_lo@Whi + h_hi@Wlo (fp32 accum in regs);
//  D staged to smem; column-walk segmented max; encoded atomicMax.
// ---------------------------------------------------------------------------
#define HS  136                 // bf16 per smem row (128 + 8 pad)
#define RB  (HS * 2)            // 272 bytes per row
#define SM_W2HI   0             // 128 x 272 B = 34816
#define SM_W2LO   34816
#define SM_H1HI   69632
#define SM_H1LO   104448        // ends 139264
#define SM_D      69632         // overlay: 128 x 132 floats = 67584 B
#define SM_SDST   139264        // 128 ints
#define SM_TILEID 139776
#define SM_TOTAL  139840

__global__ void __launch_bounds__(512, 1)
k_agg(const float* __restrict__ W2, const float* __restrict__ b2,
      int E, int ntiles)
{
    extern __shared__ char smem[];
    const unsigned sb = smem_u32(smem);
    const int t = threadIdx.x;
    const int lane = t & 31;
    const int wid = t >> 5;

    // ---- one-time: W2^T (row j = output col, k contiguous) bf16 hi/lo ----
    {
        const int j = t >> 2, q = t & 3;
#pragma unroll
        for (int i = 0; i < 32; i += 2) {
            const int k = q * 32 + i;
            const float v0 = W2[k * O + j];
            const float v1 = W2[(k + 1) * O + j];
            unsigned h;
            asm("cvt.rn.bf16x2.f32 %0, %1, %2;" : "=r"(h) : "f"(v1), "f"(v0));
            const float r0 = v0 - __uint_as_float(h << 16);
            const float r1 = v1 - __uint_as_float(h & 0xFFFF0000u);
            unsigned l;
            asm("cvt.rn.bf16x2.f32 %0, %1, %2;" : "=r"(l) : "f"(r1), "f"(r0));
            *(unsigned*)(smem + SM_W2HI + j * RB + k * 2) = h;
            *(unsigned*)(smem + SM_W2LO + j * RB + k * 2) = l;
        }
    }
    __syncthreads();

    int* sdst = (int*)(smem + SM_SDST);
    const int mw = wid & 7;              // m strip: rows 16*mw..+15
    const int nh = wid >> 3;             // n half: cols 64*nh..+63
    const int e_g = t >> 2, qq = t & 3;  // gather: edge, k-quarter
    const int jj = t & 127, sg = t >> 7; // walk: column, row-quarter
    const float b2j = b2[jj];

    // ldmatrix lane address components (x4: lanes 0-7/8-15/16-23/24-31 -> tiles)
    const unsigned lrow = (unsigned)(lane & 15);
    const unsigned lkh  = (unsigned)((lane >> 4) * 16);
    const unsigned a_off = (16u * mw + lrow) * RB + lkh;
    const unsigned b_off = (64u * nh + lrow) * RB + lkh;

    for (;;) {
        if (t == 0) *(int*)(smem + SM_TILEID) = atomicAdd(&g_tilectr, 1);
        __syncthreads();
        const int tile = *(const int*)(smem + SM_TILEID);
        if (tile >= ntiles) break;
        const int eb = tile * TILE;
        const int ne = min(TILE, E - eb);

        if (t < TILE) sdst[t] = (t < ne) ? g_edst[eb + t] : -1;

        // ---- gather + relu + bf16 hi/lo split (4 threads per edge) ----
        if (e_g < ne) {
            const int s = g_esrc[eb + e_g];
            const int c = g_edst[eb + e_g];
            const float4* Ap = (const float4*)(g_A + (size_t)s * H + qq * 32);
            const float4* Bp = (const float4*)(g_B + (size_t)c * H + qq * 32);
            float va[32];
#pragma unroll
            for (int i = 0; i < 8; i++) {
                const float4 a = Ap[i];
                const float4 b = Bp[i];
                va[4 * i + 0] = fmaxf(a.x - b.x, 0.0f);
                va[4 * i + 1] = fmaxf(a.y - b.y, 0.0f);
                va[4 * i + 2] = fmaxf(a.z - b.z, 0.0f);
                va[4 * i + 3] = fmaxf(a.w - b.w, 0.0f);
            }
            const unsigned off = (unsigned)(e_g * RB) + (unsigned)(qq * 64);
#pragma unroll
            for (int c8 = 0; c8 < 4; c8++) {
                unsigned hi[4], lo[4];
#pragma unroll
                for (int m = 0; m < 4; m++) {
                    const float v0 = va[c8 * 8 + 2 * m];
                    const float v1 = va[c8 * 8 + 2 * m + 1];
                    unsigned h;
                    asm("cvt.rn.bf16x2.f32 %0, %1, %2;"
                        : "=r"(h) : "f"(v1), "f"(v0));
                    hi[m] = h;
                    const float r0 = v0 - __uint_as_float(h << 16);
                    const float r1 = v1 - __uint_as_float(h & 0xFFFF0000u);
                    unsigned l;
                    asm("cvt.rn.bf16x2.f32 %0, %1, %2;"
                        : "=r"(l) : "f"(r1), "f"(r0));
                    lo[m] = l;
                }
                *(uint4*)(smem + SM_H1HI + off + c8 * 16) =
                    make_uint4(hi[0], hi[1], hi[2], hi[3]);
                *(uint4*)(smem + SM_H1LO + off + c8 * 16) =
                    make_uint4(lo[0], lo[1], lo[2], lo[3]);
            }
        }
        __syncthreads();

        // ---- MMA: D[16 rows x 64 cols] per warp, 3-product split-bf16 ----
        float acc[8][4];
#pragma unroll
        for (int nt = 0; nt < 8; nt++)
#pragma unroll
            for (int r = 0; r < 4; r++) acc[nt][r] = 0.0f;

#pragma unroll
        for (int ks = 0; ks < 8; ks++) {
            unsigned ahi[4], alo[4];
            ldsm4(ahi[0], ahi[1], ahi[2], ahi[3],
                  sb + SM_H1HI + a_off + ks * 32);
            ldsm4(alo[0], alo[1], alo[2], alo[3],
                  sb + SM_H1LO + a_off + ks * 32);
#pragma unroll
            for (int ntp = 0; ntp < 4; ntp++) {
                const unsigned boff = b_off + ntp * (16u * RB) + ks * 32;
                unsigned h0, h1, h2, h3, l0, l1, l2, l3;
                ldsm4(h0, h1, h2, h3, sb + SM_W2HI + boff);
                ldsm4(l0, l1, l2, l3, sb + SM_W2LO + boff);
                mma16816(acc[2 * ntp],     ahi, h0, h2);
                mma16816(acc[2 * ntp + 1], ahi, h1, h3);
                mma16816(acc[2 * ntp],     alo, h0, h2);
                mma16816(acc[2 * ntp + 1], alo, h1, h3);
                mma16816(acc[2 * ntp],     ahi, l0, l2);
                mma16816(acc[2 * ntp + 1], ahi, l1, l3);
            }
        }
        __syncthreads();   // all h1 reads done before D overlay writes

        // ---- stage D to smem (stride 132 floats) ----
        float* Dst = (float*)(smem + SM_D);
        {
            const int r = 16 * mw + (lane >> 2);
            const int cb = 64 * nh + (lane & 3) * 2;
#pragma unroll
            for (int nt = 0; nt < 8; nt++) {
                const int c = cb + nt * 8;
                *(float2*)(Dst + r * 132 + c) =
                    make_float2(acc[nt][0], acc[nt][1]);
                *(float2*)(Dst + (r + 8) * 132 + c) =
                    make_float2(acc[nt][2], acc[nt][3]);
            }
        }
        __syncthreads();

        // ---- column-walk segmented max (dst non-decreasing within tile) ----
        {
            const int e0 = sg * 32;
            const int e1 = min(e0 + 32, ne);
            if (e0 < e1) {
                int cur = sdst[e0];
                float mx = -__int_as_float(0x7f800000);
                for (int e = e0; e < e1; e++) {
                    const float v = Dst[e * 132 + jj];
                    const int dd = sdst[e];
                    if (dd != cur) {
                        atomicMax(&g_enc[(size_t)cur * O + jj], fenc(mx + b2j));
                        cur = dd;
                        mx = v;
                    } else {
                        mx = fmaxf(mx, v);
                    }
                }
                atomicMax(&g_enc[(size_t)cur * O + jj], fenc(mx + b2j));
            }
        }
        __syncthreads();
    }
}

// final: decode encoded max; empty segments -> 0
__global__ void k_decode(float* __restrict__ out, int NC)
{
    const int i = blockIdx.x * blockDim.x + threadIdx.x;
    if (i >= NC * O) return;
    const int c = i >> 7;
    out[i] = (g_rowptr[c + 1] > g_rowptr[c]) ? fdec(g_enc[i]) : 0.0f;
}

// ---------------------------------------------------------------------------
extern "C" void kernel_launch(void* const* d_in, const int* in_sizes, int n_in,
                              void* d_out, int out_size)
{
    const float* x     = (const float*)d_in[0];
    const float* pos   = (const float*)d_in[2];
    const float* pos_c = (const float*)d_in[3];
    const int*   src   = (const int*)d_in[4];
    const int*   dst   = (const int*)d_in[5];
    const float* W1    = (const float*)d_in[6];
    const float* b1    = (const float*)d_in[7];
    const float* W2    = (const float*)d_in[8];
    const float* b2    = (const float*)d_in[9];
    float* out = (float*)d_out;

    const int N  = in_sizes[0] / D;
    const int NC = in_sizes[1] / O;
    const int E  = in_sizes[4];
    const int ntiles = (E + TILE - 1) / TILE;

    k_precompute_A<<<(N + 7) / 8, 128>>>(x, pos, W1, b1, N);
    k_precompute_B<<<(NC * H + 255) / 256, 256>>>(pos_c, W1, NC);
    k_init<<<(NC * O + 255) / 256, 256>>>(NC);
    k_histogram<<<(E + 255) / 256, 256>>>(dst, E);
    k_scan<<<1, 1024>>>(NC);
    k_scatter<<<(E + 255) / 256, 256>>>(src, dst, E);

    cudaFuncSetAttribute(k_agg, cudaFuncAttributeMaxDynamicSharedMemorySize,
                         SM_TOTAL);
    k_agg<<<152, 512, SM_TOTAL>>>(W2, b2, E, ntiles);
    k_decode<<<(NC * O + 255) / 256, 256>>>(out, NC);
}

// round 6
// speedup vs baseline: 2.5237x; 1.4137x over previous
#include <cuda_runtime.h>

// Problem constants (fixed by the dataset)
#define D   64
#define P   3
#define H   128
#define O   128
#define NMAX   100000
#define NCMAX  50000
#define EMAX   1600000
#define TILE   128

// ---------------- scratch (device globals; no allocation allowed) ----------
__device__ float        g_A[NMAX * H];       // per-source layer-1 partial (+b1)
__device__ float        g_B[NCMAX * H];      // per-center layer-1 partial
__device__ int          g_rowptr[NCMAX + 1];
__device__ int          g_cursor[NCMAX];
__device__ int          g_esrc[EMAX];        // CSR-sorted src
__device__ int          g_edst[EMAX];        // CSR-sorted dst (non-decreasing)
__device__ unsigned int g_enc[NCMAX * O];    // encoded-uint running max
__device__ int          g_tilectr;           // work-stealing counter

// ======================= helpers ===========================================
__device__ __forceinline__ unsigned smem_u32(const void* p) {
    unsigned a;
    asm("{ .reg .u64 t; cvta.to.shared.u64 t, %1; cvt.u32.u64 %0, t; }"
        : "=r"(a) : "l"(p));
    return a;
}
__device__ __forceinline__ unsigned fenc(float f) {
    unsigned u = __float_as_uint(f);
    return (u & 0x80000000u) ? ~u : (u | 0x80000000u);
}
__device__ __forceinline__ float fdec(unsigned u) {
    return __uint_as_float((u & 0x80000000u) ? (u & 0x7fffffffu) : ~u);
}
#define ENC_NEG_INF 0x007FFFFFu

__device__ __forceinline__ unsigned to_tf32(float v) {
    unsigned u;
    asm("cvt.rna.tf32.f32 %0, %1;" : "=r"(u) : "f"(v));
    return u;
}
__device__ __forceinline__ void ldsm4(unsigned& r0, unsigned& r1,
                                      unsigned& r2, unsigned& r3, unsigned addr)
{
    asm volatile("ldmatrix.sync.aligned.m8n8.x4.shared.b16 {%0,%1,%2,%3}, [%4];"
                 : "=r"(r0), "=r"(r1), "=r"(r2), "=r"(r3) : "r"(addr));
}
__device__ __forceinline__ void mma_tf32(float* d, const unsigned* a,
                                         unsigned b0, unsigned b1)
{
    asm volatile("mma.sync.aligned.m16n8k8.row.col.f32.tf32.tf32.f32 "
                 "{%0,%1,%2,%3}, {%4,%5,%6,%7}, {%8,%9}, {%0,%1,%2,%3};"
                 : "+f"(d[0]), "+f"(d[1]), "+f"(d[2]), "+f"(d[3])
                 : "r"(a[0]), "r"(a[1]), "r"(a[2]), "r"(a[3]),
                   "r"(b0), "r"(b1));
}

// ---------------------------------------------------------------------------
// Fused precompute: blocks [0,nA) do A rows, blocks [nA, nA+nB) do B.
// A[n][h] = x[n] @ W1[:64] + pos[n] @ W1[64:67] + b1
// B[c][h] = pos_c[c] @ W1[64:67]
// ---------------------------------------------------------------------------
__global__ void k_pre(const float* __restrict__ x,
                      const float* __restrict__ pos,
                      const float* __restrict__ pos_c,
                      const float* __restrict__ W1,
                      const float* __restrict__ b1,
                      int N, int NC, int nA)
{
    const int tid = threadIdx.x;
    if ((int)blockIdx.x < nA) {
        __shared__ float W1s[(D + P) * H];
        __shared__ float xs[D + P];
        for (int i = tid; i < (D + P) * H; i += 128) W1s[i] = W1[i];
        const float bias = b1[tid];
        __syncthreads();
        const int base = blockIdx.x * 8;
        for (int r = 0; r < 8; r++) {
            const int n = base + r;
            if (n >= N) break;
            if (tid < D) xs[tid] = x[n * D + tid];
            if (tid < P) xs[D + tid] = pos[n * P + tid];
            __syncthreads();
            float s = bias;
#pragma unroll
            for (int d = 0; d < D + P; d++) s += xs[d] * W1s[d * H + tid];
            g_A[n * H + tid] = s;
            __syncthreads();
        }
    } else {
        const int bb = blockIdx.x - nA;
#pragma unroll
        for (int r = 0; r < 8; r++) {
            const int idx = bb * 1024 + r * 128 + tid;
            if (idx < NC * H) {
                const int c = idx >> 7;
                const int h = idx & 127;
                g_B[idx] = pos_c[c * 3 + 0] * W1[(D + 0) * H + h]
                         + pos_c[c * 3 + 1] * W1[(D + 1) * H + h]
                         + pos_c[c * 3 + 2] * W1[(D + 2) * H + h];
            }
        }
    }
}

// ------------------------- CSR + output init -------------------------------
__global__ void k_init(int NC)
{
    const int i = blockIdx.x * blockDim.x + threadIdx.x;
    if (i == 0) g_tilectr = 0;
    if (i < NC) g_cursor[i] = 0;
    if (i < NC * O) g_enc[i] = ENC_NEG_INF;
}

__global__ void k_histogram(const int* __restrict__ dst, int E)
{
    const int i = blockIdx.x * blockDim.x + threadIdx.x;
    if (i < E) atomicAdd(&g_cursor[dst[i]], 1);
}

// single-block exclusive scan, shuffle-based
__global__ void k_scan(int NC)
{
    __shared__ int wsum[32];
    __shared__ int s_carry;
    const int tid = threadIdx.x, lane = tid & 31, w = tid >> 5;
    if (tid == 0) s_carry = 0;
    __syncthreads();

    const int ntiles = (NC + 1023) >> 10;
    for (int tile = 0; tile < ntiles; tile++) {
        const int i = (tile << 10) + tid;
        const int v = (i < NC) ? g_cursor[i] : 0;
        int inc = v;
#pragma unroll
        for (int o = 1; o < 32; o <<= 1) {
            const int n = __shfl_up_sync(0xFFFFFFFFu, inc, o);
            if (lane >= o) inc += n;
        }
        if (lane == 31) wsum[w] = inc;
        __syncthreads();
        if (w == 0) {
            int xv = wsum[lane];
#pragma unroll
            for (int o = 1; o < 32; o <<= 1) {
                const int n = __shfl_up_sync(0xFFFFFFFFu, xv, o);
                if (lane >= o) xv += n;
            }
            wsum[lane] = xv;
        }
        __syncthreads();
        const int excl = s_carry + (w ? wsum[w - 1] : 0) + inc - v;
        if (i < NC) {
            g_rowptr[i] = excl;
            g_cursor[i] = excl;
        }
        __syncthreads();
        if (tid == 0) s_carry += wsum[31];
        __syncthreads();
    }
    if (tid == 0) g_rowptr[NC] = s_carry;
}

__global__ void k_scatter(const int* __restrict__ src,
                          const int* __restrict__ dst, int E)
{
    const int i = blockIdx.x * blockDim.x + threadIdx.x;
    if (i < E) {
        const int p = atomicAdd(&g_cursor[dst[i]], 1);
        g_esrc[p] = src[i];
        g_edst[p] = dst[i];
    }
}

// ---------------------------------------------------------------------------
// Aggregate via single-product tf32 mma.sync:
//  tiles of 128 CSR-sorted edges; h1 = relu(A[src]-B[dst]) (tf32, smem);
//  D = h1 @ W2 (fp32 accum in regs, 4x4 warp grid of 32x32 tiles);
//  D staged to smem (overlaying h1); column-walk segmented max -> atomicMax.
// ---------------------------------------------------------------------------
#define RSW 140                 // words per smem row (128 + 12 pad)
#define RSB 560                 // bytes per row (weight 3 mod 8 -> ldsm ok)
#define SM_W2T    0             // 128 x 560 = 71680
#define SM_H1     71680         // 128 x 560 = 71680 (D overlays)
#define SM_SDST   143360        // 128 ints
#define SM_TILEID 143872
#define SM_TOTAL  143936

__global__ void __launch_bounds__(512, 1)
k_agg(const float* __restrict__ W2, const float* __restrict__ b2,
      int E, int ntiles)
{
    extern __shared__ char smem[];
    const unsigned sb = smem_u32(smem);
    const int t = threadIdx.x;
    const int lane = t & 31;
    const int wid = t >> 5;

    // ---- one-time: W2^T (row j = output col, k contiguous) as tf32 ----
    {
        const int j = t >> 2, q4 = t & 3;
#pragma unroll
        for (int m = 0; m < 4; m++) {
            unsigned u[8];
#pragma unroll
            for (int i = 0; i < 8; i++)
                u[i] = to_tf32(W2[(8 * q4 + 32 * m + i) * O + j]);
            char* p = smem + SM_W2T + j * RSB + q4 * 32 + m * 128;
            *(uint4*)p = make_uint4(u[0], u[1], u[2], u[3]);
            *(uint4*)(p + 16) = make_uint4(u[4], u[5], u[6], u[7]);
        }
    }
    __syncthreads();

    int* sdst = (int*)(smem + SM_SDST);
    const int mr = wid & 3;              // m strip: rows 32*mr..+31
    const int nc = wid >> 2;             // n strip: cols 32*nc..+31
    const int e_g = t >> 2, q4 = t & 3;  // gather: edge, k-quarter
    const int jj = t & 127, sg = t >> 7; // walk: column, row-quarter
    const float b2j = b2[jj];

    // ldmatrix per-lane bases (tf32 trick: 4 tiles = 2 row-halves x 2 k-halves)
    const int ag = lane >> 3, alr = lane & 7;
    const unsigned a_base0 = sb + SM_H1 +
        (unsigned)((32 * mr + alr + 8 * (ag & 1)) * RSB) + (unsigned)((ag >> 1) * 16);
    const unsigned a_base1 = a_base0 + 16u * RSB;
    const unsigned b_base0 = sb + SM_W2T +
        (unsigned)((32 * nc + alr + 8 * (ag >> 1)) * RSB) + (unsigned)((ag & 1) * 16);
    const unsigned b_base1 = b_base0 + 16u * RSB;

    for (;;) {
        if (t == 0) *(int*)(smem + SM_TILEID) = atomicAdd(&g_tilectr, 1);
        __syncthreads();
        const int tile = *(const int*)(smem + SM_TILEID);
        if (tile >= ntiles) break;
        const int eb = tile * TILE;
        const int ne = min(TILE, E - eb);

        if (t < TILE) sdst[t] = (t < ne) ? g_edst[eb + t] : -1;

        // ---- gather + relu + tf32 cvt into h1 smem (4 threads per edge) ----
        if (e_g < ne) {
            const int s = g_esrc[eb + e_g];
            const int c = g_edst[eb + e_g];
            const float* Ap = g_A + (size_t)s * H;
            const float* Bp = g_B + (size_t)c * H;
            char* rowp = smem + SM_H1 + e_g * RSB + q4 * 32;
#pragma unroll
            for (int m = 0; m < 4; m++) {
                const int k0 = 8 * q4 + 32 * m;
                const float4 a0 = *(const float4*)(Ap + k0);
                const float4 a1 = *(const float4*)(Ap + k0 + 4);
                const float4 bb0 = *(const float4*)(Bp + k0);
                const float4 bb1 = *(const float4*)(Bp + k0 + 4);
                uint4 u0, u1;
                u0.x = to_tf32(fmaxf(a0.x - bb0.x, 0.0f));
                u0.y = to_tf32(fmaxf(a0.y - bb0.y, 0.0f));
                u0.z = to_tf32(fmaxf(a0.z - bb0.z, 0.0f));
                u0.w = to_tf32(fmaxf(a0.w - bb0.w, 0.0f));
                u1.x = to_tf32(fmaxf(a1.x - bb1.x, 0.0f));
                u1.y = to_tf32(fmaxf(a1.y - bb1.y, 0.0f));
                u1.z = to_tf32(fmaxf(a1.z - bb1.z, 0.0f));
                u1.w = to_tf32(fmaxf(a1.w - bb1.w, 0.0f));
                *(uint4*)(rowp + m * 128) = u0;
                *(uint4*)(rowp + m * 128 + 16) = u1;
            }
        }
        __syncthreads();

        // ---- MMA: 32x32 per warp, single-product tf32 ----
        float acc[2][4][4];
#pragma unroll
        for (int f = 0; f < 2; f++)
#pragma unroll
            for (int nb = 0; nb < 4; nb++)
#pragma unroll
                for (int r = 0; r < 4; r++) acc[f][nb][r] = 0.0f;

#pragma unroll
        for (int ks = 0; ks < 16; ks++) {
            const unsigned off = (unsigned)(ks * 32);
            unsigned af0[4], af1[4], bp0[4], bp1[4];
            ldsm4(af0[0], af0[1], af0[2], af0[3], a_base0 + off);
            ldsm4(af1[0], af1[1], af1[2], af1[3], a_base1 + off);
            ldsm4(bp0[0], bp0[1], bp0[2], bp0[3], b_base0 + off);
            ldsm4(bp1[0], bp1[1], bp1[2], bp1[3], b_base1 + off);
            mma_tf32(acc[0][0], af0, bp0[0], bp0[1]);
            mma_tf32(acc[0][1], af0, bp0[2], bp0[3]);
            mma_tf32(acc[0][2], af0, bp1[0], bp1[1]);
            mma_tf32(acc[0][3], af0, bp1[2], bp1[3]);
            mma_tf32(acc[1][0], af1, bp0[0], bp0[1]);
            mma_tf32(acc[1][1], af1, bp0[2], bp0[3]);
            mma_tf32(acc[1][2], af1, bp1[0], bp1[1]);
            mma_tf32(acc[1][3], af1, bp1[2], bp1[3]);
        }
        __syncthreads();   // all h1 reads done before D overlay writes

        // ---- stage D to smem (overlay h1, stride RSW words) ----
        float* Dst = (float*)(smem + SM_H1);
        {
            const int r0 = 32 * mr + (lane >> 2);
            const int c0 = 32 * nc + 2 * (lane & 3);
#pragma unroll
            for (int f = 0; f < 2; f++)
#pragma unroll
                for (int nb = 0; nb < 4; nb++) {
                    const int r = r0 + 16 * f;
                    const int c = c0 + 8 * nb;
                    *(float2*)(Dst + r * RSW + c) =
                        make_float2(acc[f][nb][0], acc[f][nb][1]);
                    *(float2*)(Dst + (r + 8) * RSW + c) =
                        make_float2(acc[f][nb][2], acc[f][nb][3]);
                }
        }
        __syncthreads();

        // ---- column-walk segmented max (dst non-decreasing within tile) ----
        {
            const int e0 = sg * 32;
            const int e1 = min(e0 + 32, ne);
            if (e0 < e1) {
                int cur = sdst[e0];
                float mx = -__int_as_float(0x7f800000);
                for (int e = e0; e < e1; e++) {
                    const float v = Dst[e * RSW + jj];
                    const int dd = sdst[e];
                    if (dd != cur) {
                        atomicMax(&g_enc[(size_t)cur * O + jj], fenc(mx + b2j));
                        cur = dd;
                        mx = v;
                    } else {
                        mx = fmaxf(mx, v);
                    }
                }
                atomicMax(&g_enc[(size_t)cur * O + jj], fenc(mx + b2j));
            }
        }
        __syncthreads();
    }
}

// final: decode encoded max; empty segments -> 0
__global__ void k_decode(float* __restrict__ out, int NC)
{
    const int i = blockIdx.x * blockDim.x + threadIdx.x;
    if (i >= NC * O) return;
    const int c = i >> 7;
    out[i] = (g_rowptr[c + 1] > g_rowptr[c]) ? fdec(g_enc[i]) : 0.0f;
}

// ---------------------------------------------------------------------------
extern "C" void kernel_launch(void* const* d_in, const int* in_sizes, int n_in,
                              void* d_out, int out_size)
{
    const float* x     = (const float*)d_in[0];
    const float* pos   = (const float*)d_in[2];
    const float* pos_c = (const float*)d_in[3];
    const int*   src   = (const int*)d_in[4];
    const int*   dst   = (const int*)d_in[5];
    const float* W1    = (const float*)d_in[6];
    const float* b1    = (const float*)d_in[7];
    const float* W2    = (const float*)d_in[8];
    const float* b2    = (const float*)d_in[9];
    float* out = (float*)d_out;

    const int N  = in_sizes[0] / D;
    const int NC = in_sizes[1] / O;
    const int E  = in_sizes[4];
    const int ntiles = (E + TILE - 1) / TILE;
    const int nA = (N + 7) / 8;
    const int nB = (NC * H + 1023) / 1024;

    k_pre<<<nA + nB, 128>>>(x, pos, pos_c, W1, b1, N, NC, nA);
    k_init<<<(NC * O + 255) / 256, 256>>>(NC);
    k_histogram<<<(E + 255) / 256, 256>>>(dst, E);
    k_scan<<<1, 1024>>>(NC);
    k_scatter<<<(E + 255) / 256, 256>>>(src, dst, E);

    cudaFuncSetAttribute(k_agg, cudaFuncAttributeMaxDynamicSharedMemorySize,
                         SM_TOTAL);
    k_agg<<<148, 512, SM_TOTAL>>>(W2, b2, E, ntiles);
    k_decode<<<(NC * O + 255) / 256, 256>>>(out, NC);
}